// round 1
// baseline (speedup 1.0000x reference)
#include <cuda_runtime.h>

#define N_SVC  50000
#define N_INST 100000
#define N_NODE 50000
#define FDIM   128
#define HDIM   128
#define ODIM   256
#define NTOT   200000        // SVC + NODE + INST
#define NPAD   200704        // 196 * 1024, padded for final GEMM
#define NCHUNK 196

#define E_SC 400000
#define E_IN 100000
#define E_NI 100000
#define E_II 800000

// ---- scratch (device globals: allocation-free) ----
__device__ float g_hsc[(size_t)N_SVC * HDIM];   // (feat_svc  @ W_sc) * ns
__device__ float g_hin[(size_t)N_INST * HDIM];  // (feat_inst @ W_in) * ns
__device__ float g_hni[(size_t)N_NODE * HDIM];  // (feat_node @ W_ni) * ns
__device__ float g_hii[(size_t)N_INST * HDIM];  // (feat_inst @ W_ii) * ns
__device__ float g_act[(size_t)NPAD * HDIM];    // concat buffer [svc|node|inst|pad]
__device__ float g_deg[600000];                 // 8 normalization vectors packed

// offsets into g_deg (floats)
#define OFF_NS_SC 0        // out-degree rsqrt over SVC   (svc_src)
#define OFF_ND_SC 50000    // in-degree  rsqrt over SVC   (svc_dst)
#define OFF_NS_IN 100000   // out-degree over INST        (in_src)
#define OFF_ND_IN 200000   // in-degree  over NODE        (in_dst)
#define OFF_NS_NI 250000   // out-degree over NODE        (ni_src)
#define OFF_ND_NI 300000   // in-degree  over INST        (ni_dst)
#define OFF_NS_II 400000   // out-degree over INST        (ii_src)
#define OFF_ND_II 500000   // in-degree  over INST        (ii_dst)

__global__ void k_zero(float* __restrict__ p, size_t n) {
    size_t i = (size_t)blockIdx.x * blockDim.x + threadIdx.x;
    size_t stride = (size_t)gridDim.x * blockDim.x;
    for (; i < n; i += stride) p[i] = 0.f;
}

__global__ void k_deg(const int* __restrict__ idx, float* __restrict__ deg, int n) {
    int i = blockIdx.x * blockDim.x + threadIdx.x;
    if (i < n) atomicAdd(&deg[idx[i]], 1.0f);
}

__global__ void k_rsqrt(float* __restrict__ d, int n) {
    int i = blockIdx.x * blockDim.x + threadIdx.x;
    if (i < n) d[i] = rsqrtf(fmaxf(d[i], 1.0f));
}

// H[r, :] = (X[r, :] @ W) * ns[r]     X:[nrows,128], W:[128,128] row-major
// 128 threads (one per output column h), 64 rows per block, K staged 32 at a time.
__global__ __launch_bounds__(128) void k_proj(
    const float* __restrict__ X, const float* __restrict__ W,
    const float* __restrict__ ns, float* __restrict__ Hout, int nrows)
{
    __shared__ float Ws[32][128];  // 16 KB
    __shared__ float Xs[64][32];   //  8 KB
    const int row0 = blockIdx.x * 64;
    const int h = threadIdx.x;

    float acc[64];
#pragma unroll
    for (int r = 0; r < 64; r++) acc[r] = 0.f;

    for (int kh = 0; kh < 4; kh++) {
        __syncthreads();
        // stage W rows [kh*32, kh*32+32)
        for (int i = h; i < 32 * 128; i += 128) {
            int k = i >> 7, c = i & 127;
            Ws[k][c] = W[(size_t)(kh * 32 + k) * 128 + c];
        }
        // stage X block [row0..row0+64) x [kh*32, +32)
        for (int i = h; i < 64 * 32; i += 128) {
            int r = i >> 5, c = i & 31;
            int gr = row0 + r;
            Xs[r][c] = (gr < nrows) ? X[(size_t)gr * 128 + kh * 32 + c] : 0.f;
        }
        __syncthreads();
#pragma unroll 2
        for (int k = 0; k < 32; k++) {
            float w = Ws[k][h];
#pragma unroll
            for (int r = 0; r < 64; r++) acc[r] += Xs[r][k] * w;
        }
    }
#pragma unroll
    for (int r = 0; r < 64; r++) {
        int gr = row0 + r;
        if (gr < nrows) Hout[(size_t)gr * 128 + h] = acc[r] * ns[gr];
    }
}

// one warp per edge; lane handles 4 contiguous h; agg[dst] += Hs[src] * nd[dst]
__global__ void k_scatter(const float* __restrict__ Hs, const int* __restrict__ src,
                          const int* __restrict__ dst, const float* __restrict__ nd,
                          float* __restrict__ agg, int ne)
{
    int g = blockIdx.x * blockDim.x + threadIdx.x;
    int e = g >> 5, lane = g & 31;
    if (e >= ne) return;
    int s = __ldg(&src[e]);
    int d = __ldg(&dst[e]);
    float scale = __ldg(&nd[d]);
    float4 v = ((const float4*)(Hs + (size_t)s * 128))[lane];
    float* ap = agg + (size_t)d * 128 + lane * 4;
    atomicAdd(ap + 0, v.x * scale);
    atomicAdd(ap + 1, v.y * scale);
    atomicAdd(ap + 2, v.z * scale);
    atomicAdd(ap + 3, v.w * scale);
}

// act = leaky_relu(act + bias(segment)) in place
__global__ void k_finalize(float* __restrict__ act,
                           const float* __restrict__ bsc, const float* __restrict__ bin,
                           const float* __restrict__ bni, const float* __restrict__ bii)
{
    int idx = blockIdx.x * blockDim.x + threadIdx.x;
    if (idx >= NTOT * HDIM) return;
    int row = idx >> 7, h = idx & 127;
    float b;
    if (row < N_SVC)               b = bsc[h];
    else if (row < N_SVC + N_NODE) b = bin[h];
    else                           b = bni[h] + bii[h];
    float v = act[idx] + b;
    act[idx] = (v >= 0.f) ? v : 0.01f * v;
}

__global__ void k_init_out(float* __restrict__ out, const float* __restrict__ btot) {
    int i = blockIdx.x * blockDim.x + threadIdx.x;
    if (i < ODIM * HDIM) out[i] = btot[i >> 7];
}

// out[o,h] += sum_n Wt[o,n] * act[n,h]; split-K over 1024-node chunks,
// 8 o-tiles of 32; 256 threads: thread = (o-quad, h-quad), 4x4 register tile.
__global__ __launch_bounds__(256) void k_gemm(const float* __restrict__ Wt,
                                              float* __restrict__ out)
{
    __shared__ float As[64][128];  // act stage: 32 KB
    __shared__ float Bs[32][64];   // W stage:    8 KB
    const int otile = blockIdx.x;   // 0..7
    const int chunk = blockIdx.y;   // 0..195
    const int t = threadIdx.x;
    const int h0 = (t & 31) * 4;
    const int o0 = (t >> 5) * 4;

    float acc[4][4];
#pragma unroll
    for (int j = 0; j < 4; j++)
#pragma unroll
        for (int i = 0; i < 4; i++) acc[j][i] = 0.f;

    const int nbase0 = chunk * 1024;
    for (int s = 0; s < 16; s++) {
        int nb = nbase0 + s * 64;
        __syncthreads();
        for (int i = t; i < 64 * 128; i += 256) {
            int n = i >> 7, h = i & 127;
            As[n][h] = g_act[(size_t)(nb + n) * 128 + h];  // padded: always in-bounds
        }
        for (int i = t; i < 32 * 64; i += 256) {
            int o = i >> 6, n = i & 63;
            int gn = nb + n;
            Bs[o][n] = (gn < NTOT) ? Wt[(size_t)(otile * 32 + o) * NTOT + gn] : 0.f;
        }
        __syncthreads();
#pragma unroll 4
        for (int n = 0; n < 64; n++) {
            float4 a = *(const float4*)&As[n][h0];
#pragma unroll
            for (int j = 0; j < 4; j++) {
                float w = Bs[o0 + j][n];
                acc[j][0] += w * a.x;
                acc[j][1] += w * a.y;
                acc[j][2] += w * a.z;
                acc[j][3] += w * a.w;
            }
        }
    }
#pragma unroll
    for (int j = 0; j < 4; j++)
#pragma unroll
        for (int i = 0; i < 4; i++)
            atomicAdd(&out[(otile * 32 + o0 + j) * 128 + h0 + i], acc[j][i]);
}

extern "C" void kernel_launch(void* const* d_in, const int* in_sizes, int n_in,
                              void* d_out, int out_size)
{
    (void)in_sizes; (void)n_in; (void)out_size;
    const float* feat_svc  = (const float*)d_in[0];
    const float* feat_inst = (const float*)d_in[1];
    const float* feat_node = (const float*)d_in[2];
    const int* svc_src = (const int*)d_in[3];
    const int* svc_dst = (const int*)d_in[4];
    const int* in_src  = (const int*)d_in[5];
    const int* in_dst  = (const int*)d_in[6];
    const int* ni_src  = (const int*)d_in[7];
    const int* ni_dst  = (const int*)d_in[8];
    const int* ii_src  = (const int*)d_in[9];
    const int* ii_dst  = (const int*)d_in[10];
    const float* W_sc = (const float*)d_in[11];
    const float* b_sc = (const float*)d_in[12];
    const float* W_in = (const float*)d_in[13];
    const float* b_in = (const float*)d_in[14];
    const float* W_ni = (const float*)d_in[15];
    const float* b_ni = (const float*)d_in[16];
    const float* W_ii = (const float*)d_in[17];
    const float* b_ii = (const float*)d_in[18];
    const float* W_tot = (const float*)d_in[19];
    const float* b_tot = (const float*)d_in[20];
    float* out = (float*)d_out;

    float *p_hsc, *p_hin, *p_hni, *p_hii, *p_act, *p_deg;
    cudaGetSymbolAddress((void**)&p_hsc, g_hsc);
    cudaGetSymbolAddress((void**)&p_hin, g_hin);
    cudaGetSymbolAddress((void**)&p_hni, g_hni);
    cudaGetSymbolAddress((void**)&p_hii, g_hii);
    cudaGetSymbolAddress((void**)&p_act, g_act);
    cudaGetSymbolAddress((void**)&p_deg, g_deg);

    // 1) zero accumulators + degree buffers
    k_zero<<<4096, 256>>>(p_act, (size_t)NPAD * HDIM);
    k_zero<<<1024, 256>>>(p_deg, (size_t)600000);

    // 2) degrees (counts via float atomics)
    k_deg<<<(E_SC + 255) / 256, 256>>>(svc_src, p_deg + OFF_NS_SC, E_SC);
    k_deg<<<(E_SC + 255) / 256, 256>>>(svc_dst, p_deg + OFF_ND_SC, E_SC);
    k_deg<<<(E_IN + 255) / 256, 256>>>(in_src,  p_deg + OFF_NS_IN, E_IN);
    k_deg<<<(E_IN + 255) / 256, 256>>>(in_dst,  p_deg + OFF_ND_IN, E_IN);
    k_deg<<<(E_NI + 255) / 256, 256>>>(ni_src,  p_deg + OFF_NS_NI, E_NI);
    k_deg<<<(E_NI + 255) / 256, 256>>>(ni_dst,  p_deg + OFF_ND_NI, E_NI);
    k_deg<<<(E_II + 255) / 256, 256>>>(ii_src,  p_deg + OFF_NS_II, E_II);
    k_deg<<<(E_II + 255) / 256, 256>>>(ii_dst,  p_deg + OFF_ND_II, E_II);

    // 3) deg -> rsqrt(max(deg,1))
    k_rsqrt<<<(600000 + 255) / 256, 256>>>(p_deg, 600000);

    // 4) projections (x @ W) * ns
    k_proj<<<(N_SVC  + 63) / 64, 128>>>(feat_svc,  W_sc, p_deg + OFF_NS_SC, p_hsc, N_SVC);
    k_proj<<<(N_INST + 63) / 64, 128>>>(feat_inst, W_in, p_deg + OFF_NS_IN, p_hin, N_INST);
    k_proj<<<(N_NODE + 63) / 64, 128>>>(feat_node, W_ni, p_deg + OFF_NS_NI, p_hni, N_NODE);
    k_proj<<<(N_INST + 63) / 64, 128>>>(feat_inst, W_ii, p_deg + OFF_NS_II, p_hii, N_INST);

    // 5) edge scatter with per-dst normalization (warp per edge)
    k_scatter<<<((size_t)E_SC * 32 + 255) / 256, 256>>>(p_hsc, svc_src, svc_dst,
        p_deg + OFF_ND_SC, p_act, E_SC);
    k_scatter<<<((size_t)E_IN * 32 + 255) / 256, 256>>>(p_hin, in_src, in_dst,
        p_deg + OFF_ND_IN, p_act + (size_t)N_SVC * HDIM, E_IN);
    k_scatter<<<((size_t)E_NI * 32 + 255) / 256, 256>>>(p_hni, ni_src, ni_dst,
        p_deg + OFF_ND_NI, p_act + (size_t)(N_SVC + N_NODE) * HDIM, E_NI);
    k_scatter<<<((size_t)E_II * 32 + 255) / 256, 256>>>(p_hii, ii_src, ii_dst,
        p_deg + OFF_ND_II, p_act + (size_t)(N_SVC + N_NODE) * HDIM, E_II);

    // 6) bias + leaky relu
    k_finalize<<<(NTOT * HDIM + 255) / 256, 256>>>(p_act, b_sc, b_in, b_ni, b_ii);

    // 7) final GEMM: out = W_tot @ act + b_tot[:,None]
    k_init_out<<<(ODIM * HDIM + 255) / 256, 256>>>(out, b_tot);
    dim3 gg(8, NCHUNK);
    k_gemm<<<gg, 256>>>(W_tot, out);
}

// round 2
// speedup vs baseline: 1.0031x; 1.0031x over previous
#include <cuda_runtime.h>

#define N_SVC  50000
#define N_INST 100000
#define N_NODE 50000
#define FDIM   128
#define HDIM   128
#define ODIM   256
#define NTOT   200000        // SVC + NODE + INST
#define NPAD   200704        // 196 * 1024, padded for final GEMM
#define NCHUNK 196

#define E_SC 400000
#define E_IN 100000
#define E_NI 100000
#define E_II 800000

// ---- scratch (device globals: allocation-free) ----
__device__ float g_hsc[(size_t)N_SVC * HDIM];   // (feat_svc  @ W_sc) * ns
__device__ float g_hin[(size_t)N_INST * HDIM];  // (feat_inst @ W_in) * ns
__device__ float g_hni[(size_t)N_NODE * HDIM];  // (feat_node @ W_ni) * ns
__device__ float g_hii[(size_t)N_INST * HDIM];  // (feat_inst @ W_ii) * ns
__device__ float g_act[(size_t)NPAD * HDIM];    // concat buffer [svc|node|inst|pad]
__device__ float g_deg[600000];                 // 8 normalization vectors packed

// offsets into g_deg (floats)
#define OFF_NS_SC 0        // out-degree rsqrt over SVC   (svc_src)
#define OFF_ND_SC 50000    // in-degree  rsqrt over SVC   (svc_dst)
#define OFF_NS_IN 100000   // out-degree over INST        (in_src)
#define OFF_ND_IN 200000   // in-degree  over NODE        (in_dst)
#define OFF_NS_NI 250000   // out-degree over NODE        (ni_src)
#define OFF_ND_NI 300000   // in-degree  over INST        (ni_dst)
#define OFF_NS_II 400000   // out-degree over INST        (ii_src)
#define OFF_ND_II 500000   // in-degree  over INST        (ii_dst)

__global__ void k_zero(float* __restrict__ p, size_t n) {
    size_t i = (size_t)blockIdx.x * blockDim.x + threadIdx.x;
    size_t stride = (size_t)gridDim.x * blockDim.x;
    for (; i < n; i += stride) p[i] = 0.f;
}

__global__ void k_deg(const int* __restrict__ idx, float* __restrict__ deg, int n) {
    int i = blockIdx.x * blockDim.x + threadIdx.x;
    if (i < n) atomicAdd(&deg[idx[i]], 1.0f);
}

__global__ void k_rsqrt(float* __restrict__ d, int n) {
    int i = blockIdx.x * blockDim.x + threadIdx.x;
    if (i < n) d[i] = rsqrtf(fmaxf(d[i], 1.0f));
}

// H[r, :] = (X[r, :] @ W) * ns[r]     X:[nrows,128], W:[128,128] row-major
// 128 threads (one per output column h), 64 rows per block, K staged 32 at a time.
__global__ __launch_bounds__(128) void k_proj(
    const float* __restrict__ X, const float* __restrict__ W,
    const float* __restrict__ ns, float* __restrict__ Hout, int nrows)
{
    __shared__ float Ws[32][128];  // 16 KB
    __shared__ float Xs[64][32];   //  8 KB
    const int row0 = blockIdx.x * 64;
    const int h = threadIdx.x;

    float acc[64];
#pragma unroll
    for (int r = 0; r < 64; r++) acc[r] = 0.f;

    for (int kh = 0; kh < 4; kh++) {
        __syncthreads();
        // stage W rows [kh*32, kh*32+32)
        for (int i = h; i < 32 * 128; i += 128) {
            int k = i >> 7, c = i & 127;
            Ws[k][c] = W[(size_t)(kh * 32 + k) * 128 + c];
        }
        // stage X block [row0..row0+64) x [kh*32, +32)
        for (int i = h; i < 64 * 32; i += 128) {
            int r = i >> 5, c = i & 31;
            int gr = row0 + r;
            Xs[r][c] = (gr < nrows) ? X[(size_t)gr * 128 + kh * 32 + c] : 0.f;
        }
        __syncthreads();
#pragma unroll 2
        for (int k = 0; k < 32; k++) {
            float w = Ws[k][h];
#pragma unroll
            for (int r = 0; r < 64; r++) acc[r] += Xs[r][k] * w;
        }
    }
#pragma unroll
    for (int r = 0; r < 64; r++) {
        int gr = row0 + r;
        if (gr < nrows) Hout[(size_t)gr * 128 + h] = acc[r] * ns[gr];
    }
}

// one warp per edge; lane handles 4 contiguous h; agg[dst] += Hs[src] * nd[dst]
__global__ void k_scatter(const float* __restrict__ Hs, const int* __restrict__ src,
                          const int* __restrict__ dst, const float* __restrict__ nd,
                          float* __restrict__ agg, int ne)
{
    int g = blockIdx.x * blockDim.x + threadIdx.x;
    int e = g >> 5, lane = g & 31;
    if (e >= ne) return;
    int s = __ldg(&src[e]);
    int d = __ldg(&dst[e]);
    float scale = __ldg(&nd[d]);
    float4 v = ((const float4*)(Hs + (size_t)s * 128))[lane];
    float* ap = agg + (size_t)d * 128 + lane * 4;
    atomicAdd(ap + 0, v.x * scale);
    atomicAdd(ap + 1, v.y * scale);
    atomicAdd(ap + 2, v.z * scale);
    atomicAdd(ap + 3, v.w * scale);
}

// act = leaky_relu(act + bias(segment)) in place
__global__ void k_finalize(float* __restrict__ act,
                           const float* __restrict__ bsc, const float* __restrict__ bin,
                           const float* __restrict__ bni, const float* __restrict__ bii)
{
    int idx = blockIdx.x * blockDim.x + threadIdx.x;
    if (idx >= NTOT * HDIM) return;
    int row = idx >> 7, h = idx & 127;
    float b;
    if (row < N_SVC)               b = bsc[h];
    else if (row < N_SVC + N_NODE) b = bin[h];
    else                           b = bni[h] + bii[h];
    float v = act[idx] + b;
    act[idx] = (v >= 0.f) ? v : 0.01f * v;
}

__global__ void k_init_out(float* __restrict__ out, const float* __restrict__ btot) {
    int i = blockIdx.x * blockDim.x + threadIdx.x;
    if (i < ODIM * HDIM) out[i] = btot[i >> 7];
}

// out[o,h] += sum_n Wt[o,n] * act[n,h]; split-K over 1024-node chunks,
// 8 o-tiles of 32; 256 threads: thread = (o-quad, h-quad), 4x4 register tile.
__global__ __launch_bounds__(256) void k_gemm(const float* __restrict__ Wt,
                                              float* __restrict__ out)
{
    __shared__ float As[64][128];  // act stage: 32 KB
    __shared__ float Bs[32][64];   // W stage:    8 KB
    const int otile = blockIdx.x;   // 0..7
    const int chunk = blockIdx.y;   // 0..195
    const int t = threadIdx.x;
    const int h0 = (t & 31) * 4;
    const int o0 = (t >> 5) * 4;

    float acc[4][4];
#pragma unroll
    for (int j = 0; j < 4; j++)
#pragma unroll
        for (int i = 0; i < 4; i++) acc[j][i] = 0.f;

    const int nbase0 = chunk * 1024;
    for (int s = 0; s < 16; s++) {
        int nb = nbase0 + s * 64;
        __syncthreads();
        for (int i = t; i < 64 * 128; i += 256) {
            int n = i >> 7, h = i & 127;
            As[n][h] = g_act[(size_t)(nb + n) * 128 + h];  // padded: always in-bounds
        }
        for (int i = t; i < 32 * 64; i += 256) {
            int o = i >> 6, n = i & 63;
            int gn = nb + n;
            Bs[o][n] = (gn < NTOT) ? Wt[(size_t)(otile * 32 + o) * NTOT + gn] : 0.f;
        }
        __syncthreads();
#pragma unroll 4
        for (int n = 0; n < 64; n++) {
            float4 a = *(const float4*)&As[n][h0];
#pragma unroll
            for (int j = 0; j < 4; j++) {
                float w = Bs[o0 + j][n];
                acc[j][0] += w * a.x;
                acc[j][1] += w * a.y;
                acc[j][2] += w * a.z;
                acc[j][3] += w * a.w;
            }
        }
    }
#pragma unroll
    for (int j = 0; j < 4; j++)
#pragma unroll
        for (int i = 0; i < 4; i++)
            atomicAdd(&out[(otile * 32 + o0 + j) * 128 + h0 + i], acc[j][i]);
}

extern "C" void kernel_launch(void* const* d_in, const int* in_sizes, int n_in,
                              void* d_out, int out_size)
{
    (void)in_sizes; (void)n_in; (void)out_size;
    const float* feat_svc  = (const float*)d_in[0];
    const float* feat_inst = (const float*)d_in[1];
    const float* feat_node = (const float*)d_in[2];
    const int* svc_src = (const int*)d_in[3];
    const int* svc_dst = (const int*)d_in[4];
    const int* in_src  = (const int*)d_in[5];
    const int* in_dst  = (const int*)d_in[6];
    const int* ni_src  = (const int*)d_in[7];
    const int* ni_dst  = (const int*)d_in[8];
    const int* ii_src  = (const int*)d_in[9];
    const int* ii_dst  = (const int*)d_in[10];
    const float* W_sc = (const float*)d_in[11];
    const float* b_sc = (const float*)d_in[12];
    const float* W_in = (const float*)d_in[13];
    const float* b_in = (const float*)d_in[14];
    const float* W_ni = (const float*)d_in[15];
    const float* b_ni = (const float*)d_in[16];
    const float* W_ii = (const float*)d_in[17];
    const float* b_ii = (const float*)d_in[18];
    const float* W_tot = (const float*)d_in[19];
    const float* b_tot = (const float*)d_in[20];
    float* out = (float*)d_out;

    float *p_hsc, *p_hin, *p_hni, *p_hii, *p_act, *p_deg;
    cudaGetSymbolAddress((void**)&p_hsc, g_hsc);
    cudaGetSymbolAddress((void**)&p_hin, g_hin);
    cudaGetSymbolAddress((void**)&p_hni, g_hni);
    cudaGetSymbolAddress((void**)&p_hii, g_hii);
    cudaGetSymbolAddress((void**)&p_act, g_act);
    cudaGetSymbolAddress((void**)&p_deg, g_deg);

    // 1) zero accumulators + degree buffers
    k_zero<<<4096, 256>>>(p_act, (size_t)NPAD * HDIM);
    k_zero<<<1024, 256>>>(p_deg, (size_t)600000);

    // 2) degrees (counts via float atomics)
    k_deg<<<(E_SC + 255) / 256, 256>>>(svc_src, p_deg + OFF_NS_SC, E_SC);
    k_deg<<<(E_SC + 255) / 256, 256>>>(svc_dst, p_deg + OFF_ND_SC, E_SC);
    k_deg<<<(E_IN + 255) / 256, 256>>>(in_src,  p_deg + OFF_NS_IN, E_IN);
    k_deg<<<(E_IN + 255) / 256, 256>>>(in_dst,  p_deg + OFF_ND_IN, E_IN);
    k_deg<<<(E_NI + 255) / 256, 256>>>(ni_src,  p_deg + OFF_NS_NI, E_NI);
    k_deg<<<(E_NI + 255) / 256, 256>>>(ni_dst,  p_deg + OFF_ND_NI, E_NI);
    k_deg<<<(E_II + 255) / 256, 256>>>(ii_src,  p_deg + OFF_NS_II, E_II);
    k_deg<<<(E_II + 255) / 256, 256>>>(ii_dst,  p_deg + OFF_ND_II, E_II);

    // 3) deg -> rsqrt(max(deg,1))
    k_rsqrt<<<(600000 + 255) / 256, 256>>>(p_deg, 600000);

    // 4) projections (x @ W) * ns
    k_proj<<<(N_SVC  + 63) / 64, 128>>>(feat_svc,  W_sc, p_deg + OFF_NS_SC, p_hsc, N_SVC);
    k_proj<<<(N_INST + 63) / 64, 128>>>(feat_inst, W_in, p_deg + OFF_NS_IN, p_hin, N_INST);
    k_proj<<<(N_NODE + 63) / 64, 128>>>(feat_node, W_ni, p_deg + OFF_NS_NI, p_hni, N_NODE);
    k_proj<<<(N_INST + 63) / 64, 128>>>(feat_inst, W_ii, p_deg + OFF_NS_II, p_hii, N_INST);

    // 5) edge scatter with per-dst normalization (warp per edge)
    k_scatter<<<((size_t)E_SC * 32 + 255) / 256, 256>>>(p_hsc, svc_src, svc_dst,
        p_deg + OFF_ND_SC, p_act, E_SC);
    k_scatter<<<((size_t)E_IN * 32 + 255) / 256, 256>>>(p_hin, in_src, in_dst,
        p_deg + OFF_ND_IN, p_act + (size_t)N_SVC * HDIM, E_IN);
    k_scatter<<<((size_t)E_NI * 32 + 255) / 256, 256>>>(p_hni, ni_src, ni_dst,
        p_deg + OFF_ND_NI, p_act + (size_t)(N_SVC + N_NODE) * HDIM, E_NI);
    k_scatter<<<((size_t)E_II * 32 + 255) / 256, 256>>>(p_hii, ii_src, ii_dst,
        p_deg + OFF_ND_II, p_act + (size_t)(N_SVC + N_NODE) * HDIM, E_II);

    // 6) bias + leaky relu
    k_finalize<<<(NTOT * HDIM + 255) / 256, 256>>>(p_act, b_sc, b_in, b_ni, b_ii);

    // 7) final GEMM: out = W_tot @ act + b_tot[:,None]
    k_init_out<<<(ODIM * HDIM + 255) / 256, 256>>>(out, b_tot);
    dim3 gg(8, NCHUNK);
    k_gemm<<<gg, 256>>>(W_tot, out);
}

// round 4
// speedup vs baseline: 2.6028x; 2.5949x over previous
#include <cuda_runtime.h>
#include <cuda_bf16.h>
#include <cstdint>

#define N_SVC  50000
#define N_INST 100000
#define N_NODE 50000
#define HDIM   128
#define ODIM   256
#define NTOT   200000
#define NKT    12544           // k16-tiles covering NPAD = 200704
#define NTILE_VALID 12500      // tiles with real data (NTOT/16)
#define NPAD   200704
#define GCHUNK 112             // chunks in final gemm
#define KT_PER_CHUNK 112       // k16-tiles per chunk (112*112 = 12544)

#define E_SC 400000
#define E_IN 100000
#define E_NI 100000
#define E_II 800000

// ---------------- scratch ----------------
__device__ float g_hsc[(size_t)N_SVC * HDIM];
__device__ float g_hin[(size_t)N_INST * HDIM];
__device__ float g_hni[(size_t)N_NODE * HDIM];
__device__ float g_hii[(size_t)N_INST * HDIM];
__device__ float g_act[(size_t)NPAD * HDIM];
__device__ float g_deg[600000];
// act^T fragment-ordered bf16: [tile][natom][lane] uint2 {b0,b1}
__device__ uint2 g_bth[(size_t)NKT * 512];
__device__ uint2 g_btl[(size_t)NKT * 512];
// W fragments: [relation][hi/lo][katom*512 + natom*32 + lane]
__device__ uint2 g_wfr[4][2][4096];

#define OFF_NS_SC 0
#define OFF_ND_SC 50000
#define OFF_NS_IN 100000
#define OFF_ND_IN 200000
#define OFF_NS_NI 250000
#define OFF_ND_NI 300000
#define OFF_NS_II 400000
#define OFF_ND_II 500000

// ---------------- helpers ----------------
__device__ __forceinline__ void cvt_hilo(float x, float y, uint32_t& hi, uint32_t& lo) {
    __nv_bfloat16 hx = __float2bfloat16(x), hy = __float2bfloat16(y);
    float rx = x - __bfloat162float(hx), ry = y - __bfloat162float(hy);
    __nv_bfloat16 lx = __float2bfloat16(rx), ly = __float2bfloat16(ry);
    hi = (uint32_t)__bfloat16_as_ushort(hx) | ((uint32_t)__bfloat16_as_ushort(hy) << 16);
    lo = (uint32_t)__bfloat16_as_ushort(lx) | ((uint32_t)__bfloat16_as_ushort(ly) << 16);
}

__device__ __forceinline__ void mma16816(float* c, const uint32_t* a, uint32_t b0, uint32_t b1) {
    asm volatile(
        "mma.sync.aligned.m16n8k16.row.col.f32.bf16.bf16.f32 "
        "{%0,%1,%2,%3}, {%4,%5,%6,%7}, {%8,%9}, {%0,%1,%2,%3};"
        : "+f"(c[0]), "+f"(c[1]), "+f"(c[2]), "+f"(c[3])
        : "r"(a[0]), "r"(a[1]), "r"(a[2]), "r"(a[3]), "r"(b0), "r"(b1));
}

// ---------------- small kernels ----------------
__global__ void k_zero(float* __restrict__ p, size_t n) {
    size_t i = (size_t)blockIdx.x * blockDim.x + threadIdx.x;
    size_t s = (size_t)gridDim.x * blockDim.x;
    for (; i < n; i += s) p[i] = 0.f;
}
__global__ void k_deg(const int* __restrict__ idx, float* __restrict__ deg, int n) {
    int i = blockIdx.x * blockDim.x + threadIdx.x;
    if (i < n) atomicAdd(&deg[idx[i]], 1.0f);
}
__global__ void k_rsqrt(float* __restrict__ d, int n) {
    int i = blockIdx.x * blockDim.x + threadIdx.x;
    if (i < n) d[i] = rsqrtf(fmaxf(d[i], 1.0f));
}

// W [128k x 128n] fp32 -> B fragments (hi & lo), fragment order [katom][natom][lane]
__global__ void k_prepW(const float* __restrict__ W, uint2* __restrict__ whi,
                        uint2* __restrict__ wlo) {
    int id = blockIdx.x * blockDim.x + threadIdx.x;   // 0..4095
    int katom = id >> 9, rest = id & 511;
    int natom = rest >> 5, lane = rest & 31;
    int g = lane >> 2, tig = lane & 3;
    int n = natom * 8 + g;
    int k0 = katom * 16 + 2 * tig;
    uint32_t h0, l0, h1, l1;
    cvt_hilo(W[(k0) * 128 + n], W[(k0 + 1) * 128 + n], h0, l0);
    cvt_hilo(W[(k0 + 8) * 128 + n], W[(k0 + 9) * 128 + n], h1, l1);
    whi[id] = make_uint2(h0, h1);
    wlo[id] = make_uint2(l0, l1);
}

// ---- projection: H[r,:] = (X[r,:] @ W) * ns[r], tensor-core split-bf16 ----
__global__ __launch_bounds__(256, 2) void k_proj_mma(
    const float* __restrict__ X, const uint2* __restrict__ whi,
    const uint2* __restrict__ wlo, const float* __restrict__ ns,
    float* __restrict__ Hout, int nrows)
{
    __shared__ uint2 s_wh[4096];   // 32 KB
    __shared__ uint2 s_wl[4096];   // 32 KB
    const int tid = threadIdx.x, wid = tid >> 5, lane = tid & 31;
    const int g = lane >> 2, tig = lane & 3;
    const int row0 = blockIdx.x * 128;

    // stage W fragments
    {
        const uint4* sh = (const uint4*)whi;
        const uint4* sl = (const uint4*)wlo;
#pragma unroll
        for (int j = 0; j < 8; j++) {
            ((uint4*)s_wh)[tid + 256 * j] = sh[tid + 256 * j];
            ((uint4*)s_wl)[tid + 256 * j] = sl[tid + 256 * j];
        }
    }
    __syncthreads();

    const int r0 = row0 + wid * 16 + g;
    const int r1 = r0 + 8;
    const bool v0 = (r0 < nrows), v1 = (r1 < nrows);
    const float* p0 = X + (size_t)r0 * 128;
    const float* p1 = X + (size_t)r1 * 128;

    float acc[16][4];
#pragma unroll
    for (int na = 0; na < 16; na++)
#pragma unroll
        for (int q = 0; q < 4; q++) acc[na][q] = 0.f;

    const float2 z2 = make_float2(0.f, 0.f);
#pragma unroll 1
    for (int ka = 0; ka < 8; ka++) {
        uint32_t ah[4], al[4];
        int kk = ka * 16 + 2 * tig;
        float2 x00 = v0 ? *(const float2*)(p0 + kk) : z2;
        float2 x01 = v0 ? *(const float2*)(p0 + kk + 8) : z2;
        float2 x10 = v1 ? *(const float2*)(p1 + kk) : z2;
        float2 x11 = v1 ? *(const float2*)(p1 + kk + 8) : z2;
        cvt_hilo(x00.x, x00.y, ah[0], al[0]);
        cvt_hilo(x10.x, x10.y, ah[1], al[1]);
        cvt_hilo(x01.x, x01.y, ah[2], al[2]);
        cvt_hilo(x11.x, x11.y, ah[3], al[3]);
#pragma unroll
        for (int na = 0; na < 16; na++) {
            uint2 bh = s_wh[(ka * 16 + na) * 32 + lane];
            uint2 bl = s_wl[(ka * 16 + na) * 32 + lane];
            mma16816(acc[na], ah, bh.x, bh.y);
            mma16816(acc[na], al, bh.x, bh.y);
            mma16816(acc[na], ah, bl.x, bl.y);
        }
    }

    float s0 = v0 ? ns[r0] : 0.f;
    float s1 = v1 ? ns[r1] : 0.f;
#pragma unroll
    for (int na = 0; na < 16; na++) {
        int col = na * 8 + 2 * tig;
        if (v0) *(float2*)(Hout + (size_t)r0 * 128 + col) =
            make_float2(acc[na][0] * s0, acc[na][1] * s0);
        if (v1) *(float2*)(Hout + (size_t)r1 * 128 + col) =
            make_float2(acc[na][2] * s1, acc[na][3] * s1);
    }
}

// ---- edge scatter: agg[dst] += Hs[src] * nd[dst], vector reductions ----
__global__ void k_scatter(const float* __restrict__ Hs, const int* __restrict__ src,
                          const int* __restrict__ dst, const float* __restrict__ nd,
                          float* __restrict__ agg, int ne) {
    int gidx = blockIdx.x * blockDim.x + threadIdx.x;
    int e = gidx >> 5, lane = gidx & 31;
    if (e >= ne) return;
    int s = __ldg(&src[e]);
    int d = __ldg(&dst[e]);
    float scale = __ldg(&nd[d]);
    float4 v = ((const float4*)(Hs + (size_t)s * 128))[lane];
    float* ap = agg + (size_t)d * 128 + lane * 4;
    asm volatile("red.global.add.v4.f32 [%0], {%1, %2, %3, %4};"
                 :: "l"(ap), "f"(v.x * scale), "f"(v.y * scale),
                    "f"(v.z * scale), "f"(v.w * scale) : "memory");
}

// ---- pack: act + bias -> leakyrelu -> bf16 hi/lo fragment order ----
__global__ __launch_bounds__(128) void k_pack(const float* __restrict__ act,
                                              const float* __restrict__ bsc,
                                              const float* __restrict__ bin,
                                              const float* __restrict__ bni,
                                              const float* __restrict__ bii,
                                              uint2* __restrict__ bth,
                                              uint2* __restrict__ btl) {
    __shared__ float s[16][128];
    int t = blockIdx.x;
    int row0 = t * 16;
    int h = threadIdx.x;
    if (row0 < NTOT) {
        float bv;
        if (row0 < N_SVC)               bv = bsc[h];
        else if (row0 < N_SVC + N_NODE) bv = bin[h];
        else                            bv = bni[h] + bii[h];
#pragma unroll
        for (int r = 0; r < 16; r++) {
            float v = act[(size_t)(row0 + r) * 128 + h] + bv;
            s[r][h] = (v >= 0.f) ? v : 0.01f * v;
        }
    } else {
#pragma unroll
        for (int r = 0; r < 16; r++) s[r][h] = 0.f;
    }
    __syncthreads();
#pragma unroll
    for (int j = 0; j < 4; j++) {
        int id = h + 128 * j;                // natom*32 + lane
        int lane = id & 31;
        int natom = id >> 5;
        int gg = lane >> 2, tig = lane & 3;
        int n = natom * 8 + gg;
        uint32_t h0, l0, h1, l1;
        cvt_hilo(s[2 * tig][n], s[2 * tig + 1][n], h0, l0);
        cvt_hilo(s[2 * tig + 8][n], s[2 * tig + 9][n], h1, l1);
        size_t o = (size_t)t * 512 + id;
        bth[o] = make_uint2(h0, h1);
        btl[o] = make_uint2(l0, l1);
    }
}

__global__ void k_init_out(float* __restrict__ out, const float* __restrict__ btot) {
    int i = blockIdx.x * blockDim.x + threadIdx.x;
    if (i < ODIM * HDIM) out[i] = btot[i >> 7];
}

// ---- final GEMM: out[256,128] += W_tot @ act, split-K, tensor-core split-bf16 ----
__global__ __launch_bounds__(256, 2) void k_gemm_mma(const float* __restrict__ Wt,
                                                     const uint2* __restrict__ bth,
                                                     const uint2* __restrict__ btl,
                                                     float* __restrict__ out) {
    __shared__ uint2 s_bh[4096];   // 8 k16-tiles of B hi (32 KB)
    __shared__ uint2 s_bl[4096];   // lo (32 KB)
    const int tid = threadIdx.x, wid = tid >> 5, lane = tid & 31;
    const int g = lane >> 2, tig = lane & 3;
    const int chunk = blockIdx.x, mblk = blockIdx.y;

    const int r0 = mblk * 128 + wid * 16 + g;
    const int r1 = r0 + 8;
    const float* p0 = Wt + (size_t)r0 * NTOT;
    const float* p1 = Wt + (size_t)r1 * NTOT;

    float acc[16][4];
#pragma unroll
    for (int na = 0; na < 16; na++)
#pragma unroll
        for (int q = 0; q < 4; q++) acc[na][q] = 0.f;

    for (int sit = 0; sit < KT_PER_CHUNK / 8; sit++) {
        int tile0 = chunk * KT_PER_CHUNK + sit * 8;
        __syncthreads();
        {
            const uint4* sh = (const uint4*)(bth + (size_t)tile0 * 512);
            const uint4* sl = (const uint4*)(btl + (size_t)tile0 * 512);
#pragma unroll
            for (int j = 0; j < 8; j++) {
                ((uint4*)s_bh)[tid + 256 * j] = sh[tid + 256 * j];
                ((uint4*)s_bl)[tid + 256 * j] = sl[tid + 256 * j];
            }
        }
        __syncthreads();
        if (tile0 >= NTILE_VALID) continue;   // pure padding super-iter
#pragma unroll 1
        for (int kt = 0; kt < 8; kt++) {
            int ktg = tile0 + kt;
            if (ktg >= NTILE_VALID) break;
            uint32_t ah[4], al[4];
            size_t kk = (size_t)ktg * 16 + 2 * tig;
            float2 x00 = *(const float2*)(p0 + kk);
            float2 x01 = *(const float2*)(p0 + kk + 8);
            float2 x10 = *(const float2*)(p1 + kk);
            float2 x11 = *(const float2*)(p1 + kk + 8);
            cvt_hilo(x00.x, x00.y, ah[0], al[0]);
            cvt_hilo(x10.x, x10.y, ah[1], al[1]);
            cvt_hilo(x01.x, x01.y, ah[2], al[2]);
            cvt_hilo(x11.x, x11.y, ah[3], al[3]);
#pragma unroll
            for (int na = 0; na < 16; na++) {
                uint2 bh = s_bh[(kt * 16 + na) * 32 + lane];
                uint2 bl = s_bl[(kt * 16 + na) * 32 + lane];
                mma16816(acc[na], ah, bh.x, bh.y);
                mma16816(acc[na], al, bh.x, bh.y);
                mma16816(acc[na], ah, bl.x, bl.y);
            }
        }
    }

    // epilogue: split-K accumulate via vector reductions
#pragma unroll
    for (int na = 0; na < 16; na++) {
        int col = na * 8 + 2 * tig;
        float* d0 = out + (size_t)r0 * 128 + col;
        float* d1 = out + (size_t)r1 * 128 + col;
        asm volatile("red.global.add.v2.f32 [%0], {%1, %2};"
                     :: "l"(d0), "f"(acc[na][0]), "f"(acc[na][1]) : "memory");
        asm volatile("red.global.add.v2.f32 [%0], {%1, %2};"
                     :: "l"(d1), "f"(acc[na][2]), "f"(acc[na][3]) : "memory");
    }
}

// ---------------- host ----------------
extern "C" void kernel_launch(void* const* d_in, const int* in_sizes, int n_in,
                              void* d_out, int out_size) {
    (void)in_sizes; (void)n_in; (void)out_size;
    const float* feat_svc  = (const float*)d_in[0];
    const float* feat_inst = (const float*)d_in[1];
    const float* feat_node = (const float*)d_in[2];
    const int* svc_src = (const int*)d_in[3];
    const int* svc_dst = (const int*)d_in[4];
    const int* in_src  = (const int*)d_in[5];
    const int* in_dst  = (const int*)d_in[6];
    const int* ni_src  = (const int*)d_in[7];
    const int* ni_dst  = (const int*)d_in[8];
    const int* ii_src  = (const int*)d_in[9];
    const int* ii_dst  = (const int*)d_in[10];
    const float* W_sc = (const float*)d_in[11];
    const float* b_sc = (const float*)d_in[12];
    const float* W_in = (const float*)d_in[13];
    const float* b_in = (const float*)d_in[14];
    const float* W_ni = (const float*)d_in[15];
    const float* b_ni = (const float*)d_in[16];
    const float* W_ii = (const float*)d_in[17];
    const float* b_ii = (const float*)d_in[18];
    const float* W_tot = (const float*)d_in[19];
    const float* b_tot = (const float*)d_in[20];
    float* out = (float*)d_out;

    float *p_hsc, *p_hin, *p_hni, *p_hii, *p_act, *p_deg;
    uint2 *p_bth, *p_btl, *p_wfr;
    cudaGetSymbolAddress((void**)&p_hsc, g_hsc);
    cudaGetSymbolAddress((void**)&p_hin, g_hin);
    cudaGetSymbolAddress((void**)&p_hni, g_hni);
    cudaGetSymbolAddress((void**)&p_hii, g_hii);
    cudaGetSymbolAddress((void**)&p_act, g_act);
    cudaGetSymbolAddress((void**)&p_deg, g_deg);
    cudaGetSymbolAddress((void**)&p_bth, g_bth);
    cudaGetSymbolAddress((void**)&p_btl, g_btl);
    cudaGetSymbolAddress((void**)&p_wfr, g_wfr);

    // 1) zero act (valid rows) + degree buffers
    k_zero<<<4096, 256>>>(p_act, (size_t)NTOT * HDIM);
    k_zero<<<1024, 256>>>(p_deg, (size_t)600000);

    // 2) degrees + rsqrt
    k_deg<<<(E_SC + 255) / 256, 256>>>(svc_src, p_deg + OFF_NS_SC, E_SC);
    k_deg<<<(E_SC + 255) / 256, 256>>>(svc_dst, p_deg + OFF_ND_SC, E_SC);
    k_deg<<<(E_IN + 255) / 256, 256>>>(in_src,  p_deg + OFF_NS_IN, E_IN);
    k_deg<<<(E_IN + 255) / 256, 256>>>(in_dst,  p_deg + OFF_ND_IN, E_IN);
    k_deg<<<(E_NI + 255) / 256, 256>>>(ni_src,  p_deg + OFF_NS_NI, E_NI);
    k_deg<<<(E_NI + 255) / 256, 256>>>(ni_dst,  p_deg + OFF_ND_NI, E_NI);
    k_deg<<<(E_II + 255) / 256, 256>>>(ii_src,  p_deg + OFF_NS_II, E_II);
    k_deg<<<(E_II + 255) / 256, 256>>>(ii_dst,  p_deg + OFF_ND_II, E_II);
    k_rsqrt<<<(600000 + 255) / 256, 256>>>(p_deg, 600000);

    // 3) W -> bf16 hi/lo fragments
    k_prepW<<<16, 256>>>(W_sc, p_wfr + 0 * 8192, p_wfr + 0 * 8192 + 4096);
    k_prepW<<<16, 256>>>(W_in, p_wfr + 1 * 8192, p_wfr + 1 * 8192 + 4096);
    k_prepW<<<16, 256>>>(W_ni, p_wfr + 2 * 8192, p_wfr + 2 * 8192 + 4096);
    k_prepW<<<16, 256>>>(W_ii, p_wfr + 3 * 8192, p_wfr + 3 * 8192 + 4096);

    // 4) projections (tensor cores)
    k_proj_mma<<<(N_SVC  + 127) / 128, 256>>>(feat_svc,  p_wfr + 0 * 8192, p_wfr + 0 * 8192 + 4096, p_deg + OFF_NS_SC, p_hsc, N_SVC);
    k_proj_mma<<<(N_INST + 127) / 128, 256>>>(feat_inst, p_wfr + 1 * 8192, p_wfr + 1 * 8192 + 4096, p_deg + OFF_NS_IN, p_hin, N_INST);
    k_proj_mma<<<(N_NODE + 127) / 128, 256>>>(feat_node, p_wfr + 2 * 8192, p_wfr + 2 * 8192 + 4096, p_deg + OFF_NS_NI, p_hni, N_NODE);
    k_proj_mma<<<(N_INST + 127) / 128, 256>>>(feat_inst, p_wfr + 3 * 8192, p_wfr + 3 * 8192 + 4096, p_deg + OFF_NS_II, p_hii, N_INST);

    // 5) edge scatter (vector atomics)
    k_scatter<<<((size_t)E_SC * 32 + 255) / 256, 256>>>(p_hsc, svc_src, svc_dst, p_deg + OFF_ND_SC, p_act, E_SC);
    k_scatter<<<((size_t)E_IN * 32 + 255) / 256, 256>>>(p_hin, in_src, in_dst, p_deg + OFF_ND_IN, p_act + (size_t)N_SVC * HDIM, E_IN);
    k_scatter<<<((size_t)E_NI * 32 + 255) / 256, 256>>>(p_hni, ni_src, ni_dst, p_deg + OFF_ND_NI, p_act + (size_t)(N_SVC + N_NODE) * HDIM, E_NI);
    k_scatter<<<((size_t)E_II * 32 + 255) / 256, 256>>>(p_hii, ii_src, ii_dst, p_deg + OFF_ND_II, p_act + (size_t)(N_SVC + N_NODE) * HDIM, E_II);

    // 6) fused bias + leakyrelu + bf16 hi/lo fragment pack
    k_pack<<<NKT, 128>>>(p_act, b_sc, b_in, b_ni, b_ii, p_bth, p_btl);

    // 7) final GEMM
    k_init_out<<<(ODIM * HDIM + 255) / 256, 256>>>(out, b_tot);
    dim3 gg(GCHUNK, 2);
    k_gemm_mma<<<gg, 256>>>(W_tot, p_bth, p_btl, out);
}